// round 1
// baseline (speedup 1.0000x reference)
#include <cuda_runtime.h>
#include <math.h>

#define Mtot  4096   // B*S
#define Hdim  768
#define FFdim 3072
#define NHnum 12
#define DHdim 64
#define Sdim  512
#define Bdim  8
#define Ldim  9
#define NLnum 12

// ---------------- scratch (static device allocations) ----------------
__device__ float g_h[Mtot * Hdim];
__device__ float g_q[Mtot * Hdim];
__device__ float g_k[Mtot * Hdim];
__device__ float g_v[Mtot * Hdim];
__device__ float g_ctx[Mtot * Hdim];
__device__ float g_t[Mtot * Hdim];
__device__ float g_ff[Mtot * FFdim];
__device__ float g_feats[Mtot * Ldim];
__device__ float g_logZ[Bdim];
__device__ float g_num[Bdim];
__device__ int   g_tags[Bdim * Sdim];

// ---------------- helpers ----------------
__device__ __forceinline__ float blk_sum256(float v, float* red) {
    int lane = threadIdx.x & 31, w = threadIdx.x >> 5;
#pragma unroll
    for (int o = 16; o; o >>= 1) v += __shfl_xor_sync(0xffffffffu, v, o);
    __syncthreads();
    if (lane == 0) red[w] = v;
    __syncthreads();
    float s = 0.f;
#pragma unroll
    for (int i = 0; i < 8; i++) s += red[i];
    return s;
}

// ---------------- embedding + LayerNorm ----------------
__global__ void embed_ln_kernel(const float* __restrict__ we, const float* __restrict__ pe,
                                const float* __restrict__ te, const float* __restrict__ gs,
                                const float* __restrict__ gb, const int* __restrict__ ids,
                                const int* __restrict__ tts, float* __restrict__ out) {
    __shared__ float red[8];
    int m = blockIdx.x;
    int s = m & (Sdim - 1);
    int id = ids[m], tt = tts[m];
    float vals[3];
    float lsum = 0.f;
#pragma unroll
    for (int u = 0; u < 3; u++) {
        int j = threadIdx.x + u * 256;
        float v = we[(size_t)id * Hdim + j] + pe[(size_t)s * Hdim + j] + te[(size_t)tt * Hdim + j];
        vals[u] = v;
        lsum += v;
    }
    float mean = blk_sum256(lsum, red) * (1.f / Hdim);
    float lsq = 0.f;
#pragma unroll
    for (int u = 0; u < 3; u++) { float d = vals[u] - mean; lsq += d * d; }
    float var = blk_sum256(lsq, red) * (1.f / Hdim);
    float inv = rsqrtf(var + 1e-12f);
#pragma unroll
    for (int u = 0; u < 3; u++) {
        int j = threadIdx.x + u * 256;
        out[(size_t)m * Hdim + j] = (vals[u] - mean) * inv * gs[j] + gb[j];
    }
}

// ---------------- LayerNorm (row of H) ----------------
__global__ void ln_kernel(const float* __restrict__ x, const float* __restrict__ gs,
                          const float* __restrict__ gb, float* __restrict__ y) {
    __shared__ float red[8];
    int m = blockIdx.x;
    const float* xr = x + (size_t)m * Hdim;
    float vals[3];
    float lsum = 0.f;
#pragma unroll
    for (int u = 0; u < 3; u++) {
        vals[u] = xr[threadIdx.x + u * 256];
        lsum += vals[u];
    }
    float mean = blk_sum256(lsum, red) * (1.f / Hdim);
    float lsq = 0.f;
#pragma unroll
    for (int u = 0; u < 3; u++) { float d = vals[u] - mean; lsq += d * d; }
    float var = blk_sum256(lsq, red) * (1.f / Hdim);
    float inv = rsqrtf(var + 1e-12f);
#pragma unroll
    for (int u = 0; u < 3; u++) {
        int j = threadIdx.x + u * 256;
        y[(size_t)m * Hdim + j] = (vals[u] - mean) * inv * gs[j] + gb[j];
    }
}

// ---------------- generic fp32 GEMM: C = act(A@B + bias (+ res)) ----------------
// A: M x K row-major, B: K x N row-major. M,N multiples of 128; K multiple of 16.
template <int ACT>
__global__ void __launch_bounds__(256) gemm_kernel(const float* __restrict__ A,
                                                   const float* __restrict__ Bm,
                                                   const float* __restrict__ bias,
                                                   const float* __restrict__ res,
                                                   float* __restrict__ C, int N, int K) {
    __shared__ float As[16][128];
    __shared__ float Bs[16][128];
    const int tid = threadIdx.x;
    const int m0 = blockIdx.y * 128;
    const int n0 = blockIdx.x * 128;
    const int ty = tid >> 4, tx = tid & 15;
    float acc[8][8];
#pragma unroll
    for (int i = 0; i < 8; i++)
#pragma unroll
        for (int j = 0; j < 8; j++) acc[i][j] = 0.f;

    for (int k0 = 0; k0 < K; k0 += 16) {
#pragma unroll
        for (int l = 0; l < 2; l++) {
            int i = tid + l * 256;
            int r = i >> 2, c4 = i & 3;
            float4 v = *(const float4*)(A + (size_t)(m0 + r) * K + k0 + c4 * 4);
            As[c4 * 4 + 0][r] = v.x;
            As[c4 * 4 + 1][r] = v.y;
            As[c4 * 4 + 2][r] = v.z;
            As[c4 * 4 + 3][r] = v.w;
        }
#pragma unroll
        for (int l = 0; l < 2; l++) {
            int i = tid + l * 256;
            int r = i >> 5, c4 = i & 31;
            float4 v = *(const float4*)(Bm + (size_t)(k0 + r) * N + n0 + c4 * 4);
            *(float4*)(&Bs[r][c4 * 4]) = v;
        }
        __syncthreads();
#pragma unroll
        for (int kk = 0; kk < 16; kk++) {
            float a[8], b[8];
            *(float4*)(a)     = *(const float4*)(&As[kk][ty * 8]);
            *(float4*)(a + 4) = *(const float4*)(&As[kk][ty * 8 + 4]);
            *(float4*)(b)     = *(const float4*)(&Bs[kk][tx * 8]);
            *(float4*)(b + 4) = *(const float4*)(&Bs[kk][tx * 8 + 4]);
#pragma unroll
            for (int i = 0; i < 8; i++)
#pragma unroll
                for (int j = 0; j < 8; j++) acc[i][j] += a[i] * b[j];
        }
        __syncthreads();
    }
#pragma unroll
    for (int i = 0; i < 8; i++) {
        int row = m0 + ty * 8 + i;
#pragma unroll
        for (int j = 0; j < 8; j++) {
            int col = n0 + tx * 8 + j;
            float v = acc[i][j] + bias[col];
            if (res) v += res[(size_t)row * N + col];
            if (ACT == 1) v = 0.5f * v * (1.f + erff(v * 0.70710678118654752440f));
            C[(size_t)row * N + col] = v;
        }
    }
}

// ---------------- attention: one block per (64 q rows, head, batch) ----------------
// dynamic smem: sc[64][512] + qT[64][64] + kT[64][64]  = 163840 bytes
__global__ void __launch_bounds__(256) attn_kernel(const float* __restrict__ Q,
                                                   const float* __restrict__ Kp,
                                                   const float* __restrict__ Vp,
                                                   const int* __restrict__ amask,
                                                   float* __restrict__ O) {
    extern __shared__ float sm[];
    float* sc = sm;                       // 64*512
    float* qT = sm + 64 * 512;            // [d][q]
    float* kT = qT + 64 * 64;             // [d][k] for K phase, [k][d] for V phase
    const int tid = threadIdx.x;
    const int q0 = blockIdx.x * 64;
    const int h = blockIdx.y;
    const int b = blockIdx.z;
    const size_t base = (size_t)b * Sdim * Hdim + h * 64;
    const int ty = tid >> 4, tx = tid & 15;

    // load Q tile transposed: qT[d][q]
    for (int i = tid; i < 1024; i += 256) {
        int r = i >> 4, c4 = i & 15;
        float4 v = *(const float4*)(Q + base + (size_t)(q0 + r) * Hdim + c4 * 4);
        qT[(c4 * 4 + 0) * 64 + r] = v.x;
        qT[(c4 * 4 + 1) * 64 + r] = v.y;
        qT[(c4 * 4 + 2) * 64 + r] = v.z;
        qT[(c4 * 4 + 3) * 64 + r] = v.w;
    }

    // scores: S = Q @ K^T, tile by 64 keys
    for (int kt = 0; kt < 8; kt++) {
        int k0 = kt * 64;
        __syncthreads();
        for (int i = tid; i < 1024; i += 256) {
            int r = i >> 4, c4 = i & 15;
            float4 v = *(const float4*)(Kp + base + (size_t)(k0 + r) * Hdim + c4 * 4);
            kT[(c4 * 4 + 0) * 64 + r] = v.x;
            kT[(c4 * 4 + 1) * 64 + r] = v.y;
            kT[(c4 * 4 + 2) * 64 + r] = v.z;
            kT[(c4 * 4 + 3) * 64 + r] = v.w;
        }
        __syncthreads();
        float acc[4][4];
#pragma unroll
        for (int i = 0; i < 4; i++)
#pragma unroll
            for (int j = 0; j < 4; j++) acc[i][j] = 0.f;
        for (int d = 0; d < 64; d++) {
            float a[4], bb[4];
            *(float4*)a  = *(const float4*)(&qT[d * 64 + ty * 4]);
            *(float4*)bb = *(const float4*)(&kT[d * 64 + tx * 4]);
#pragma unroll
            for (int i = 0; i < 4; i++)
#pragma unroll
                for (int j = 0; j < 4; j++) acc[i][j] += a[i] * bb[j];
        }
#pragma unroll
        for (int i = 0; i < 4; i++) {
            float4 v = make_float4(acc[i][0], acc[i][1], acc[i][2], acc[i][3]);
            *(float4*)(&sc[(ty * 4 + i) * 512 + k0 + tx * 4]) = v;
        }
    }
    __syncthreads();

    // softmax over 512 keys per row; 4-thread teams
    {
        int row = tid >> 2, lane = tid & 3;
        float mx = -1e30f;
        for (int k = lane; k < 512; k += 4) {
            float mb = (1.f - (float)amask[b * Sdim + k]) * -10000.f;
            float v = sc[row * 512 + k] * 0.125f + mb;
            sc[row * 512 + k] = v;
            mx = fmaxf(mx, v);
        }
        mx = fmaxf(mx, __shfl_xor_sync(0xffffffffu, mx, 1, 4));
        mx = fmaxf(mx, __shfl_xor_sync(0xffffffffu, mx, 2, 4));
        float sum = 0.f;
        for (int k = lane; k < 512; k += 4) {
            float e = expf(sc[row * 512 + k] - mx);
            sc[row * 512 + k] = e;
            sum += e;
        }
        sum += __shfl_xor_sync(0xffffffffu, sum, 1, 4);
        sum += __shfl_xor_sync(0xffffffffu, sum, 2, 4);
        float inv = 1.f / sum;
        for (int k = lane; k < 512; k += 4) sc[row * 512 + k] *= inv;
    }

    // ctx = P @ V
    float acc[4][4];
#pragma unroll
    for (int i = 0; i < 4; i++)
#pragma unroll
        for (int j = 0; j < 4; j++) acc[i][j] = 0.f;
    for (int kt = 0; kt < 8; kt++) {
        int k0 = kt * 64;
        __syncthreads();
        for (int i = tid; i < 1024; i += 256) {
            int r = i >> 4, c4 = i & 15;
            float4 v = *(const float4*)(Vp + base + (size_t)(k0 + r) * Hdim + c4 * 4);
            *(float4*)(&kT[r * 64 + c4 * 4]) = v;   // [k][d]
        }
        __syncthreads();
        for (int kk = 0; kk < 64; kk++) {
            float bb[4];
            *(float4*)bb = *(const float4*)(&kT[kk * 64 + tx * 4]);
            float p0 = sc[(ty * 4 + 0) * 512 + k0 + kk];
            float p1 = sc[(ty * 4 + 1) * 512 + k0 + kk];
            float p2 = sc[(ty * 4 + 2) * 512 + k0 + kk];
            float p3 = sc[(ty * 4 + 3) * 512 + k0 + kk];
#pragma unroll
            for (int j = 0; j < 4; j++) {
                acc[0][j] += p0 * bb[j];
                acc[1][j] += p1 * bb[j];
                acc[2][j] += p2 * bb[j];
                acc[3][j] += p3 * bb[j];
            }
        }
    }
#pragma unroll
    for (int i = 0; i < 4; i++) {
        float4 v = make_float4(acc[i][0], acc[i][1], acc[i][2], acc[i][3]);
        *(float4*)(O + base + (size_t)(q0 + ty * 4 + i) * Hdim + tx * 4) = v;
    }
}

// ---------------- classifier: feats = h @ clf_W + clf_b ----------------
__global__ void clf_kernel(const float* __restrict__ X, const float* __restrict__ W,
                           const float* __restrict__ bias, float* __restrict__ F) {
    __shared__ float red[8][Ldim];
    int m = blockIdx.x;
    int tid = threadIdx.x;
    float acc[Ldim];
#pragma unroll
    for (int j = 0; j < Ldim; j++) acc[j] = 0.f;
    for (int k = tid; k < Hdim; k += 256) {
        float x = X[(size_t)m * Hdim + k];
#pragma unroll
        for (int j = 0; j < Ldim; j++) acc[j] += x * W[k * Ldim + j];
    }
    int lane = tid & 31, w = tid >> 5;
#pragma unroll
    for (int j = 0; j < Ldim; j++)
#pragma unroll
        for (int o = 16; o; o >>= 1) acc[j] += __shfl_down_sync(0xffffffffu, acc[j], o);
    if (lane == 0)
#pragma unroll
        for (int j = 0; j < Ldim; j++) red[w][j] = acc[j];
    __syncthreads();
    if (tid < Ldim) {
        float s = bias[tid];
#pragma unroll
        for (int ww = 0; ww < 8; ww++) s += red[ww][tid];
        F[(size_t)m * Ldim + tid] = s;
    }
}

// ---------------- CRF numerator ----------------
__global__ void crf_num_kernel(const float* __restrict__ feats, const int* __restrict__ amask,
                               const int* __restrict__ labels, const float* __restrict__ start,
                               const float* __restrict__ endv, const float* __restrict__ trans,
                               float* __restrict__ num) {
    __shared__ float red[8];
    int b = blockIdx.x;
    int tid = threadIdx.x;
    float s = 0.f, msum = 0.f;
    for (int t = tid; t < Sdim; t += 256) {
        int tag = labels[b * Sdim + t];
        float em = feats[(size_t)(b * Sdim + t) * Ldim + tag];
        float m = (float)amask[b * Sdim + t];
        msum += m;
        if (t == 0) {
            s += start[tag] + em;
        } else {
            int pt = labels[b * Sdim + t - 1];
            s += (em + trans[pt * Ldim + tag]) * m;
        }
    }
    float stotal = blk_sum256(s, red);
    float mtotal = blk_sum256(msum, red);
    if (tid == 0) {
        int last = (int)(mtotal + 0.5f) - 1;
        num[b] = stotal + endv[labels[b * Sdim + last]];
    }
}

// ---------------- CRF forward (logZ): warp per batch ----------------
__global__ void crf_fwd_kernel(const float* __restrict__ feats, const int* __restrict__ amask,
                               const float* __restrict__ start, const float* __restrict__ endv,
                               const float* __restrict__ trans, float* __restrict__ logZ) {
    int b = threadIdx.x >> 5;
    int j = threadIdx.x & 31;
    bool act = j < Ldim;
    float tr[Ldim];
#pragma unroll
    for (int i = 0; i < Ldim; i++) tr[i] = act ? trans[i * Ldim + j] : 0.f;
    float score = act ? start[j] + feats[(size_t)(b * Sdim) * Ldim + j] : -1e30f;
    for (int t = 1; t < Sdim; t++) {
        float e = act ? feats[(size_t)(b * Sdim + t) * Ldim + j] : 0.f;
        int m = amask[b * Sdim + t];
        float v[Ldim];
        float mx = -1e30f;
#pragma unroll
        for (int i = 0; i < Ldim; i++) {
            float si = __shfl_sync(0xffffffffu, score, i);
            v[i] = si + tr[i];
            mx = fmaxf(mx, v[i]);
        }
        float ssum = 0.f;
#pragma unroll
        for (int i = 0; i < Ldim; i++) ssum += expf(v[i] - mx);
        float nxt = mx + logf(ssum) + e;
        if (act && m > 0) score = nxt;
    }
    float tot = act ? score + endv[j] : -1e30f;
    float mx = tot;
#pragma unroll
    for (int o = 16; o; o >>= 1) mx = fmaxf(mx, __shfl_xor_sync(0xffffffffu, mx, o));
    float ex = act ? expf(tot - mx) : 0.f;
#pragma unroll
    for (int o = 16; o; o >>= 1) ex += __shfl_xor_sync(0xffffffffu, ex, o);
    if (j == 0) logZ[b] = mx + logf(ex);
}

// ---------------- Viterbi: one warp-block per batch, hist in smem ----------------
__global__ void viterbi_kernel(const float* __restrict__ feats, const int* __restrict__ amask,
                               const float* __restrict__ start, const float* __restrict__ endv,
                               const float* __restrict__ trans, int* __restrict__ tags) {
    __shared__ unsigned char hist[(Sdim - 1) * Ldim];
    int b = blockIdx.x;
    int j = threadIdx.x;
    bool act = j < Ldim;
    float tr[Ldim];
#pragma unroll
    for (int i = 0; i < Ldim; i++) tr[i] = act ? trans[i * Ldim + j] : 0.f;
    float score = act ? start[j] + feats[(size_t)(b * Sdim) * Ldim + j] : -1e30f;
    for (int t = 1; t < Sdim; t++) {
        float e = act ? feats[(size_t)(b * Sdim + t) * Ldim + j] : 0.f;
        int m = amask[b * Sdim + t];
        float best = -1e30f;
        int barg = 0;
#pragma unroll
        for (int i = 0; i < Ldim; i++) {
            float si = __shfl_sync(0xffffffffu, score, i);
            float v = si + tr[i];
            if (v > best) { best = v; barg = i; }
        }
        if (act) {
            hist[(t - 1) * Ldim + j] = (unsigned char)barg;
            float nxt = best + e;
            if (m > 0) score = nxt;
        }
    }
    __syncwarp();
    float tot = act ? score + endv[j] : -1e30f;
    float bb = tot;
    int bj = act ? j : 0;
#pragma unroll
    for (int o = 16; o; o >>= 1) {
        float ov = __shfl_down_sync(0xffffffffu, bb, o);
        int oj = __shfl_down_sync(0xffffffffu, bj, o);
        if (ov > bb) { bb = ov; bj = oj; }
    }
    if (j == 0) {
        int tag = bj;
        tags[b * Sdim + Sdim - 1] = tag;
        for (int t = Sdim - 2; t >= 0; t--) {
            tag = hist[t * Ldim + tag];
            tags[b * Sdim + t] = tag;
        }
    }
}

// ---------------- finalize: write loss + tags to d_out ----------------
__global__ void finalize_kernel(const float* __restrict__ logZ, const float* __restrict__ num,
                                const int* __restrict__ tags, float* __restrict__ out,
                                int out_size) {
    int i = blockIdx.x * blockDim.x + threadIdx.x;
    if (i >= out_size) return;
    if (i == 0) {
        float s = 0.f;
        for (int b = 0; b < Bdim; b++) s += logZ[b] - num[b];
        out[0] = s * (1.f / Bdim);
    } else if (i - 1 < Bdim * Sdim) {
        out[i] = (float)tags[i - 1];
    } else {
        out[i] = 0.f;
    }
}

// ---------------- host launch ----------------
extern "C" void kernel_launch(void* const* d_in, const int* in_sizes, int n_in,
                              void* d_out, int out_size) {
    const float* word_emb = (const float*)d_in[0];
    const float* pos_emb  = (const float*)d_in[1];
    const float* type_emb = (const float*)d_in[2];
    const float* eln_s    = (const float*)d_in[3];
    const float* eln_b    = (const float*)d_in[4];
    const float* Wq = (const float*)d_in[5];
    const float* bq = (const float*)d_in[6];
    const float* Wk = (const float*)d_in[7];
    const float* bk = (const float*)d_in[8];
    const float* Wv = (const float*)d_in[9];
    const float* bv = (const float*)d_in[10];
    const float* Wo = (const float*)d_in[11];
    const float* bo = (const float*)d_in[12];
    const float* ln1s = (const float*)d_in[13];
    const float* ln1b = (const float*)d_in[14];
    const float* W1 = (const float*)d_in[15];
    const float* b1 = (const float*)d_in[16];
    const float* W2 = (const float*)d_in[17];
    const float* b2 = (const float*)d_in[18];
    const float* ln2s = (const float*)d_in[19];
    const float* ln2b = (const float*)d_in[20];
    const float* clfW = (const float*)d_in[21];
    const float* clfb = (const float*)d_in[22];
    const float* crf_start = (const float*)d_in[23];
    const float* crf_end   = (const float*)d_in[24];
    const float* crf_trans = (const float*)d_in[25];
    const int* input_ids   = (const int*)d_in[26];
    const int* token_type  = (const int*)d_in[27];
    const int* attn_mask   = (const int*)d_in[28];
    const int* labels      = (const int*)d_in[29];

    float *h, *q, *k, *v, *ctx, *t, *ff, *feats, *logZ, *num;
    int* tags;
    cudaGetSymbolAddress((void**)&h, g_h);
    cudaGetSymbolAddress((void**)&q, g_q);
    cudaGetSymbolAddress((void**)&k, g_k);
    cudaGetSymbolAddress((void**)&v, g_v);
    cudaGetSymbolAddress((void**)&ctx, g_ctx);
    cudaGetSymbolAddress((void**)&t, g_t);
    cudaGetSymbolAddress((void**)&ff, g_ff);
    cudaGetSymbolAddress((void**)&feats, g_feats);
    cudaGetSymbolAddress((void**)&logZ, g_logZ);
    cudaGetSymbolAddress((void**)&num, g_num);
    cudaGetSymbolAddress((void**)&tags, g_tags);

    const int attn_smem = (64 * 512 + 64 * 64 + 64 * 64) * 4;  // 163840
    cudaFuncSetAttribute(attn_kernel, cudaFuncAttributeMaxDynamicSharedMemorySize, attn_smem);

    embed_ln_kernel<<<Mtot, 256>>>(word_emb, pos_emb, type_emb, eln_s, eln_b,
                                   input_ids, token_type, h);

    dim3 gProj(Hdim / 128, Mtot / 128);
    dim3 gFF1(FFdim / 128, Mtot / 128);
    dim3 gAttn(Sdim / 64, NHnum, Bdim);

    for (int l = 0; l < NLnum; l++) {
        const float* wq = Wq + (size_t)l * Hdim * Hdim;
        const float* wk = Wk + (size_t)l * Hdim * Hdim;
        const float* wv = Wv + (size_t)l * Hdim * Hdim;
        const float* wo = Wo + (size_t)l * Hdim * Hdim;
        const float* w1 = W1 + (size_t)l * Hdim * FFdim;
        const float* w2 = W2 + (size_t)l * FFdim * Hdim;

        gemm_kernel<0><<<gProj, 256>>>(h, wq, bq + l * Hdim, nullptr, q, Hdim, Hdim);
        gemm_kernel<0><<<gProj, 256>>>(h, wk, bk + l * Hdim, nullptr, k, Hdim, Hdim);
        gemm_kernel<0><<<gProj, 256>>>(h, wv, bv + l * Hdim, nullptr, v, Hdim, Hdim);

        attn_kernel<<<gAttn, 256, attn_smem>>>(q, k, v, attn_mask, ctx);

        gemm_kernel<0><<<gProj, 256>>>(ctx, wo, bo + l * Hdim, h, t, Hdim, Hdim);
        ln_kernel<<<Mtot, 256>>>(t, ln1s + l * Hdim, ln1b + l * Hdim, h);

        gemm_kernel<1><<<gFF1, 256>>>(h, w1, b1 + l * FFdim, nullptr, ff, FFdim, Hdim);
        gemm_kernel<0><<<gProj, 256>>>(ff, w2, b2 + l * Hdim, h, t, Hdim, FFdim);
        ln_kernel<<<Mtot, 256>>>(t, ln2s + l * Hdim, ln2b + l * Hdim, h);
    }

    clf_kernel<<<Mtot, 256>>>(h, clfW, clfb, feats);
    crf_num_kernel<<<Bdim, 256>>>(feats, attn_mask, labels, crf_start, crf_end, crf_trans, num);
    crf_fwd_kernel<<<1, 256>>>(feats, attn_mask, crf_start, crf_end, crf_trans, logZ);
    viterbi_kernel<<<Bdim, 32>>>(feats, attn_mask, crf_start, crf_end, crf_trans, tags);

    int nfin = (out_size + 255) / 256;
    if (nfin < 1) nfin = 1;
    finalize_kernel<<<nfin, 256>>>(logZ, num, tags, (float*)d_out, out_size);
}

// round 2
// speedup vs baseline: 1.5301x; 1.5301x over previous
#include <cuda_runtime.h>
#include <cuda_bf16.h>
#include <math.h>

#define Mtot  4096
#define Hdim  768
#define FFdim 3072
#define NHnum 12
#define DHdim 64
#define Sdim  512
#define Bdim  8
#define Ldim  9
#define NLnum 12

#define KE_H  (3 * Hdim)    // 2304
#define KE_FF (3 * FFdim)   // 9216

// ---------------- scratch (static device allocations) ----------------
__device__ float g_h[Mtot * Hdim];
__device__ float g_q[Mtot * Hdim];
__device__ float g_k[Mtot * Hdim];
__device__ float g_v[Mtot * Hdim];
__device__ float g_t[Mtot * Hdim];
__device__ float g_feats[Mtot * Ldim];
__device__ float g_logZ[Bdim];
__device__ float g_num[Bdim];
__device__ int   g_tags[Bdim * Sdim];

// split-bf16 ext activations (A operands): [M][3K], slots per k: ah, al, ah
__device__ __align__(256) __nv_bfloat16 g_hext[Mtot * KE_H];
__device__ __align__(256) __nv_bfloat16 g_ctxext[Mtot * KE_H];
__device__ __align__(256) __nv_bfloat16 g_ffext[(size_t)Mtot * KE_FF];

// packed split-bf16 weights (B operands): [3K/2][N] u32, pair=(ext row 2i, 2i+1)
// slots per k: bh, bh, bl
#define PKH (3 * Hdim / 2)    // 1152
#define PKF (3 * FFdim / 2)   // 4608
__device__ __align__(256) unsigned int g_Wqp[NLnum * PKH * Hdim];
__device__ __align__(256) unsigned int g_Wkp[NLnum * PKH * Hdim];
__device__ __align__(256) unsigned int g_Wvp[NLnum * PKH * Hdim];
__device__ __align__(256) unsigned int g_Wop[NLnum * PKH * Hdim];
__device__ __align__(256) unsigned int g_W1p[(size_t)NLnum * PKH * FFdim];
__device__ __align__(256) unsigned int g_W2p[(size_t)NLnum * PKF * Hdim];

// ---------------- helpers ----------------
__device__ __forceinline__ float blk_sum256(float v, float* red) {
    int lane = threadIdx.x & 31, w = threadIdx.x >> 5;
#pragma unroll
    for (int o = 16; o; o >>= 1) v += __shfl_xor_sync(0xffffffffu, v, o);
    __syncthreads();
    if (lane == 0) red[w] = v;
    __syncthreads();
    float s = 0.f;
#pragma unroll
    for (int i = 0; i < 8; i++) s += red[i];
    return s;
}

__device__ __forceinline__ void split2(float x, __nv_bfloat16& hi, __nv_bfloat16& lo) {
    hi = __float2bfloat16(x);
    lo = __float2bfloat16(x - __bfloat162float(hi));
}

__device__ __forceinline__ void write_ext3(__nv_bfloat16* p, float x) {
    __nv_bfloat16 h, l;
    split2(x, h, l);
    p[0] = h; p[1] = l; p[2] = h;   // A-ext slots: ah, al, ah
}

// ---------------- weight conversion: fp32 [L][K][N] -> packed [L][3K/2][N] u32 ---
__global__ void convB_kernel(const float* __restrict__ W, unsigned int* __restrict__ out,
                             int K, int N, int L) {
    size_t PK = (size_t)3 * K / 2;
    size_t total = (size_t)L * PK * N;
    for (size_t idx = (size_t)blockIdx.x * blockDim.x + threadIdx.x; idx < total;
         idx += (size_t)gridDim.x * blockDim.x) {
        int n = (int)(idx % N);
        size_t rest = idx / N;
        int i = (int)(rest % PK);
        int l = (int)(rest / PK);
        int s0 = 2 * i, s1 = 2 * i + 1;
        int k0 = s0 / 3, r0 = s0 % 3;
        int k1 = s1 / 3, r1 = s1 % 3;
        float w0 = W[((size_t)l * K + k0) * N + n];
        float w1 = W[((size_t)l * K + k1) * N + n];
        __nv_bfloat16 h0, l0, h1, l1;
        split2(w0, h0, l0);
        split2(w1, h1, l1);
        __nv_bfloat16 v0 = (r0 == 2) ? l0 : h0;   // B-ext slots: bh, bh, bl
        __nv_bfloat16 v1 = (r1 == 2) ? l1 : h1;
        __nv_bfloat162 pr(v0, v1);                // .x = low half = smaller ext row
        out[idx] = *reinterpret_cast<unsigned int*>(&pr);
    }
}

// ---------------- embedding + LayerNorm ----------------
__global__ void embed_ln_kernel(const float* __restrict__ we, const float* __restrict__ pe,
                                const float* __restrict__ te, const float* __restrict__ gs,
                                const float* __restrict__ gb, const int* __restrict__ ids,
                                const int* __restrict__ tts, float* __restrict__ out,
                                __nv_bfloat16* __restrict__ ext) {
    __shared__ float red[8];
    int m = blockIdx.x;
    int s = m & (Sdim - 1);
    int id = ids[m], tt = tts[m];
    float vals[3];
    float lsum = 0.f;
#pragma unroll
    for (int u = 0; u < 3; u++) {
        int j = threadIdx.x + u * 256;
        float v = we[(size_t)id * Hdim + j] + pe[(size_t)s * Hdim + j] + te[(size_t)tt * Hdim + j];
        vals[u] = v;
        lsum += v;
    }
    float mean = blk_sum256(lsum, red) * (1.f / Hdim);
    float lsq = 0.f;
#pragma unroll
    for (int u = 0; u < 3; u++) { float d = vals[u] - mean; lsq += d * d; }
    float var = blk_sum256(lsq, red) * (1.f / Hdim);
    float inv = rsqrtf(var + 1e-12f);
#pragma unroll
    for (int u = 0; u < 3; u++) {
        int j = threadIdx.x + u * 256;
        float y = (vals[u] - mean) * inv * gs[j] + gb[j];
        out[(size_t)m * Hdim + j] = y;
        write_ext3(ext + (size_t)m * KE_H + 3 * j, y);
    }
}

// ---------------- LayerNorm ----------------
__global__ void ln_kernel(const float* __restrict__ x, const float* __restrict__ gs,
                          const float* __restrict__ gb, float* __restrict__ y,
                          __nv_bfloat16* __restrict__ ext) {
    __shared__ float red[8];
    int m = blockIdx.x;
    const float* xr = x + (size_t)m * Hdim;
    float vals[3];
    float lsum = 0.f;
#pragma unroll
    for (int u = 0; u < 3; u++) {
        vals[u] = xr[threadIdx.x + u * 256];
        lsum += vals[u];
    }
    float mean = blk_sum256(lsum, red) * (1.f / Hdim);
    float lsq = 0.f;
#pragma unroll
    for (int u = 0; u < 3; u++) { float d = vals[u] - mean; lsq += d * d; }
    float var = blk_sum256(lsq, red) * (1.f / Hdim);
    float inv = rsqrtf(var + 1e-12f);
#pragma unroll
    for (int u = 0; u < 3; u++) {
        int j = threadIdx.x + u * 256;
        float yy = (vals[u] - mean) * inv * gs[j] + gb[j];
        y[(size_t)m * Hdim + j] = yy;
        write_ext3(ext + (size_t)m * KE_H + 3 * j, yy);
    }
}

// ================= tensor-core GEMM (split-bf16, K extended 3x) =================
#define BM 128
#define BN 128
#define BKE 96                 // ext bf16 k per tile
#define BKP 48                 // packed pair-rows per tile
#define AS_STRIDE 52           // u32 words per A smem row (48 data + 4 pad)
#define BS_STRIDE 136          // u32 words per B smem row (128 data + 8 pad)
#define STAGE_WORDS (128 * AS_STRIDE + BKP * BS_STRIDE)  // 13184
#define NSTAGE 3
#define GEMM_SMEM (NSTAGE * STAGE_WORDS * 4)             // 158208 B

__device__ __forceinline__ void cp16(unsigned int saddr, const void* gptr) {
    asm volatile("cp.async.cg.shared.global [%0], [%1], 16;\n" ::"r"(saddr), "l"(gptr));
}
__device__ __forceinline__ void cp_commit() { asm volatile("cp.async.commit_group;\n"); }
__device__ __forceinline__ void cp_wait1() { asm volatile("cp.async.wait_group 1;\n"); }

#define MMA16816(d, a, b)                                                      \
    asm volatile(                                                              \
        "mma.sync.aligned.m16n8k16.row.col.f32.bf16.bf16.f32 "                 \
        "{%0,%1,%2,%3}, {%4,%5,%6,%7}, {%8,%9}, {%0,%1,%2,%3};\n"              \
        : "+f"(d[0]), "+f"(d[1]), "+f"(d[2]), "+f"(d[3])                       \
        : "r"(a[0]), "r"(a[1]), "r"(a[2]), "r"(a[3]), "r"(b[0]), "r"(b[1]))

__device__ __forceinline__ void gemm_core(const __nv_bfloat16* __restrict__ A,
                                          const unsigned int* __restrict__ B,
                                          const float* __restrict__ bias,
                                          const float* __restrict__ resid,
                                          float* __restrict__ Cf,
                                          __nv_bfloat16* __restrict__ Ce,
                                          int N, int KE, int act, int addres, int outp,
                                          unsigned int* smem) {
    const int tid = threadIdx.x;
    const int lane = tid & 31;
    const int wid = tid >> 5;
    const int warp_m = wid >> 2;   // 0..1
    const int warp_n = wid & 3;    // 0..3
    const int m0 = blockIdx.y * BM;
    const int n0 = blockIdx.x * BN;
    const int T = KE / BKE;
    const int g = lane >> 2, t4 = lane & 3;
    const unsigned int sbase = (unsigned int)__cvta_generic_to_shared(smem);

    float acc[4][4][4];
#pragma unroll
    for (int i = 0; i < 4; i++)
#pragma unroll
        for (int j = 0; j < 4; j++)
#pragma unroll
            for (int r = 0; r < 4; r++) acc[i][j][r] = 0.f;

    // ---- load stage macro-ish lambdas ----
    auto load_stage = [&](int tile, int stg) {
        unsigned int abase = sbase + (unsigned int)(stg * STAGE_WORDS) * 4u;
        unsigned int bbase = abase + 128u * AS_STRIDE * 4u;
        const __nv_bfloat16* Ag = A + (size_t)m0 * KE + tile * BKE;
#pragma unroll
        for (int l = 0; l < 6; l++) {
            int i = tid + l * 256;
            int r = i / 12, c = i % 12;              // 128 rows x 12 chunks(16B)
            cp16(abase + (unsigned int)(r * AS_STRIDE + c * 4) * 4u,
                 Ag + (size_t)r * KE + c * 8);
        }
        const unsigned int* Bg = B + (size_t)(tile * BKP) * N + n0;
#pragma unroll
        for (int l = 0; l < 6; l++) {
            int i = tid + l * 256;
            int r = i / 32, c = i % 32;              // 48 rows x 32 chunks(16B)
            cp16(bbase + (unsigned int)(r * BS_STRIDE + c * 4) * 4u,
                 Bg + (size_t)r * N + c * 4);
        }
    };

    load_stage(0, 0); cp_commit();
    load_stage(1, 1); cp_commit();

    for (int t = 0; t < T; t++) {
        cp_wait1();
        __syncthreads();
        if (t + 2 < T) load_stage(t + 2, (t + 2) % NSTAGE);
        cp_commit();

        const unsigned int* As = smem + (size_t)(t % NSTAGE) * STAGE_WORDS;
        const unsigned int* Bs = As + 128 * AS_STRIDE;
#pragma unroll
        for (int s = 0; s < 6; s++) {
            unsigned int a[4][4], b[4][2];
#pragma unroll
            for (int mi = 0; mi < 4; mi++) {
                int r = warp_m * 64 + mi * 16 + g;
                int cp = s * 8 + t4;
                a[mi][0] = As[r * AS_STRIDE + cp];
                a[mi][1] = As[(r + 8) * AS_STRIDE + cp];
                a[mi][2] = As[r * AS_STRIDE + cp + 4];
                a[mi][3] = As[(r + 8) * AS_STRIDE + cp + 4];
            }
#pragma unroll
            for (int nj = 0; nj < 4; nj++) {
                int n = warp_n * 32 + nj * 8 + g;
                b[nj][0] = Bs[(s * 8 + t4) * BS_STRIDE + n];
                b[nj][1] = Bs[(s * 8 + t4 + 4) * BS_STRIDE + n];
            }
#pragma unroll
            for (int mi = 0; mi < 4; mi++)
#pragma unroll
                for (int nj = 0; nj < 4; nj++) MMA16816(acc[mi][nj], a[mi], b[nj]);
        }
    }

    // ---- epilogue ----
#pragma unroll
    for (int mi = 0; mi < 4; mi++) {
        int row0 = m0 + warp_m * 64 + mi * 16 + g;
#pragma unroll
        for (int nj = 0; nj < 4; nj++) {
            int col = n0 + warp_n * 32 + nj * 8 + t4 * 2;
#pragma unroll
            for (int half = 0; half < 2; half++) {
                int row = row0 + half * 8;
                float v0 = acc[mi][nj][half * 2 + 0] + bias[col];
                float v1 = acc[mi][nj][half * 2 + 1] + bias[col + 1];
                if (addres) {
                    v0 += resid[(size_t)row * N + col];
                    v1 += resid[(size_t)row * N + col + 1];
                }
                if (act) {
                    v0 = 0.5f * v0 * (1.f + erff(v0 * 0.70710678118654752440f));
                    v1 = 0.5f * v1 * (1.f + erff(v1 * 0.70710678118654752440f));
                }
                if (outp == 0) {
                    Cf[(size_t)row * N + col] = v0;
                    Cf[(size_t)row * N + col + 1] = v1;
                } else {
                    __nv_bfloat16* p = Ce + (size_t)row * (3 * N) + 3 * col;
                    write_ext3(p, v0);
                    write_ext3(p + 3, v1);
                }
            }
        }
    }
}

__global__ void __launch_bounds__(256) gemm_k1(const __nv_bfloat16* __restrict__ A,
                                               const unsigned int* __restrict__ B,
                                               const float* __restrict__ bias,
                                               const float* __restrict__ resid,
                                               float* __restrict__ Cf,
                                               __nv_bfloat16* __restrict__ Ce,
                                               int N, int KE, int act, int addres, int outp) {
    extern __shared__ unsigned int smem[];
    gemm_core(A, B, bias, resid, Cf, Ce, N, KE, act, addres, outp, smem);
}

__global__ void __launch_bounds__(256) gemm_k3(const __nv_bfloat16* __restrict__ A,
                                               const unsigned int* __restrict__ B0,
                                               const unsigned int* __restrict__ B1,
                                               const unsigned int* __restrict__ B2,
                                               const float* __restrict__ bias0,
                                               const float* __restrict__ bias1,
                                               const float* __restrict__ bias2,
                                               float* __restrict__ C0, float* __restrict__ C1,
                                               float* __restrict__ C2, int KE) {
    extern __shared__ unsigned int smem[];
    int z = blockIdx.z;
    const unsigned int* B = (z == 0) ? B0 : (z == 1) ? B1 : B2;
    const float* bias = (z == 0) ? bias0 : (z == 1) ? bias1 : bias2;
    float* Cf = (z == 0) ? C0 : (z == 1) ? C1 : C2;
    gemm_core(A, B, bias, nullptr, Cf, nullptr, Hdim, KE, 0, 0, 0, smem);
}

// ---------------- attention (fp32 SIMT; epilogue emits split-bf16 ext) ----------------
__global__ void __launch_bounds__(256) attn_kernel(const float* __restrict__ Q,
                                                   const float* __restrict__ Kp,
                                                   const float* __restrict__ Vp,
                                                   const int* __restrict__ amask,
                                                   __nv_bfloat16* __restrict__ Oext) {
    extern __shared__ float sm[];
    float* sc = sm;
    float* qT = sm + 64 * 512;
    float* kT = qT + 64 * 64;
    const int tid = threadIdx.x;
    const int q0 = blockIdx.x * 64;
    const int h = blockIdx.y;
    const int b = blockIdx.z;
    const size_t base = (size_t)b * Sdim * Hdim + h * 64;
    const int ty = tid >> 4, tx = tid & 15;

    for (int i = tid; i < 1024; i += 256) {
        int r = i >> 4, c4 = i & 15;
        float4 v = *(const float4*)(Q + base + (size_t)(q0 + r) * Hdim + c4 * 4);
        qT[(c4 * 4 + 0) * 64 + r] = v.x;
        qT[(c4 * 4 + 1) * 64 + r] = v.y;
        qT[(c4 * 4 + 2) * 64 + r] = v.z;
        qT[(c4 * 4 + 3) * 64 + r] = v.w;
    }

    for (int kt = 0; kt < 8; kt++) {
        int k0 = kt * 64;
        __syncthreads();
        for (int i = tid; i < 1024; i += 256) {
            int r = i >> 4, c4 = i & 15;
            float4 v = *(const float4*)(Kp + base + (size_t)(k0 + r) * Hdim + c4 * 4);
            kT[(c4 * 4 + 0) * 64 + r] = v.x;
            kT[(c4 * 4 + 1) * 64 + r] = v.y;
            kT[(c4 * 4 + 2) * 64 + r] = v.z;
            kT[(c4 * 4 + 3) * 64 + r] = v.w;
        }
        __syncthreads();
        float acc[4][4];
#pragma unroll
        for (int i = 0; i < 4; i++)
#pragma unroll
            for (int j = 0; j < 4; j++) acc[i][j] = 0.f;
        for (int d = 0; d < 64; d++) {
            float a[4], bb[4];
            *(float4*)a = *(const float4*)(&qT[d * 64 + ty * 4]);
            *(float4*)bb = *(const float4*)(&kT[d * 64 + tx * 4]);
#pragma unroll
            for (int i = 0; i < 4; i++)
#pragma unroll
                for (int j = 0; j < 4; j++) acc[i][j] += a[i] * bb[j];
        }
#pragma unroll
        for (int i = 0; i < 4; i++) {
            float4 v = make_float4(acc[i][0], acc[i][1], acc[i][2], acc[i][3]);
            *(float4*)(&sc[(ty * 4 + i) * 512 + k0 + tx * 4]) = v;
        }
    }
    __syncthreads();

    {
        int row = tid >> 2, lane = tid & 3;
        float mx = -1e30f;
        for (int k = lane; k < 512; k += 4) {
            float mb = (1.f - (float)amask[b * Sdim + k]) * -10000.f;
            float v = sc[row * 512 + k] * 0.125f + mb;
            sc[row * 512 + k] = v;
            mx = fmaxf(mx, v);
        }
        mx = fmaxf(mx, __shfl_xor_sync(0xffffffffu, mx, 1, 4));
        mx = fmaxf(mx, __shfl_xor_sync(0xffffffffu, mx, 2, 4));
        float sum = 0.f;
        for (int k = lane; k < 512; k += 4) {
            float e = expf(sc[row * 512 + k] - mx);
            sc[row * 512 + k] = e;
            sum += e;
        }
        sum += __shfl_xor_sync(0xffffffffu, sum, 1, 4);
        sum += __shfl_xor_sync(0xffffffffu, sum, 2, 4);
        float inv = 1.f / sum;
        for (int k = lane; k < 512; k += 4) sc[row * 512 + k] *= inv;
    }

    float acc[4][4];
#pragma unroll
    for (int i = 0; i < 4; i++)
#pragma unroll
        for (int j = 0; j < 4; j++) acc[i][j] = 0.f;
    for (int kt = 0; kt < 8; kt++) {
        int k0 = kt * 64;
        __syncthreads();
        for (int i = tid; i < 1024; i += 256) {
            int r = i >> 4, c4 = i & 15;
            float4 v = *(const float4*)(Vp + base + (size_t)(k0 + r) * Hdim + c4 * 4);
            *(float4*)(&kT[r * 64 + c4 * 4]) = v;
        }
        __syncthreads();
        for (int kk = 0; kk < 64; kk++) {
            float bb[4];
            *(float4*)bb = *(const float4*)(&kT[kk * 64 + tx * 4]);
            float p0 = sc[(ty * 4 + 0) * 512 + k0 + kk];
            float p1 = sc[(ty * 4 + 1) * 512 + k0 + kk];
            float p2 = sc[(ty * 4 + 2) * 512 + k0 + kk];
            float p3 = sc[(ty * 4 + 3) * 512 + k0 + kk];
#pragma unroll
            for (int j = 0; j < 4; j++) {
                acc[0][j] += p0 * bb[j];
                acc[1][j] += p1 * bb[j];
                acc[2][j] += p2 * bb[j];
                acc[3][j] += p3 * bb[j];
            }
        }
    }
#pragma unroll
    for (int i = 0; i < 4; i++) {
        int m = b * Sdim + q0 + ty * 4 + i;
        int colbase = h * 64 + tx * 4;
        __nv_bfloat16* p = Oext + (size_t)m * KE_H + 3 * colbase;
#pragma unroll
        for (int j = 0; j < 4; j++) write_ext3(p + 3 * j, acc[i][j]);
    }
}

// ---------------- classifier ----------------
__global__ void clf_kernel(const float* __restrict__ X, const float* __restrict__ W,
                           const float* __restrict__ bias, float* __restrict__ F) {
    __shared__ float red[8][Ldim];
    int m = blockIdx.x;
    int tid = threadIdx.x;
    float acc[Ldim];
#pragma unroll
    for (int j = 0; j < Ldim; j++) acc[j] = 0.f;
    for (int k = tid; k < Hdim; k += 256) {
        float x = X[(size_t)m * Hdim + k];
#pragma unroll
        for (int j = 0; j < Ldim; j++) acc[j] += x * W[k * Ldim + j];
    }
    int lane = tid & 31, w = tid >> 5;
#pragma unroll
    for (int j = 0; j < Ldim; j++)
#pragma unroll
        for (int o = 16; o; o >>= 1) acc[j] += __shfl_down_sync(0xffffffffu, acc[j], o);
    if (lane == 0)
#pragma unroll
        for (int j = 0; j < Ldim; j++) red[w][j] = acc[j];
    __syncthreads();
    if (tid < Ldim) {
        float s = bias[tid];
#pragma unroll
        for (int ww = 0; ww < 8; ww++) s += red[ww][tid];
        F[(size_t)m * Ldim + tid] = s;
    }
}

// ---------------- CRF numerator ----------------
__global__ void crf_num_kernel(const float* __restrict__ feats, const int* __restrict__ amask,
                               const int* __restrict__ labels, const float* __restrict__ start,
                               const float* __restrict__ endv, const float* __restrict__ trans,
                               float* __restrict__ num) {
    __shared__ float red[8];
    int b = blockIdx.x;
    int tid = threadIdx.x;
    float s = 0.f, msum = 0.f;
    for (int t = tid; t < Sdim; t += 256) {
        int tag = labels[b * Sdim + t];
        float em = feats[(size_t)(b * Sdim + t) * Ldim + tag];
        float m = (float)amask[b * Sdim + t];
        msum += m;
        if (t == 0) {
            s += start[tag] + em;
        } else {
            int pt = labels[b * Sdim + t - 1];
            s += (em + trans[pt * Ldim + tag]) * m;
        }
    }
    float stotal = blk_sum256(s, red);
    float mtotal = blk_sum256(msum, red);
    if (tid == 0) {
        int last = (int)(mtotal + 0.5f) - 1;
        num[b] = stotal + endv[labels[b * Sdim + last]];
    }
}

// ---------------- CRF forward ----------------
__global__ void crf_fwd_kernel(const float* __restrict__ feats, const int* __restrict__ amask,
                               const float* __restrict__ start, const float* __restrict__ endv,
                               const float* __restrict__ trans, float* __restrict__ logZ) {
    int b = threadIdx.x >> 5;
    int j = threadIdx.x & 31;
    bool act = j < Ldim;
    float tr[Ldim];
#pragma unroll
    for (int i = 0; i < Ldim; i++) tr[i] = act ? trans[i * Ldim + j] : 0.f;
    float score = act ? start[j] + feats[(size_t)(b * Sdim) * Ldim + j] : -1e30f;
    for (int t = 1; t < Sdim; t++) {
        float e = act ? feats[(size_t)(b * Sdim + t) * Ldim + j] : 0.f;
        int m = amask[b * Sdim + t];
        float v[Ldim];
        float mx = -1e30f;
#pragma unroll
        for (int i = 0; i < Ldim; i++) {
            float si = __shfl_sync(0xffffffffu, score, i);
            v[i] = si + tr[i];
            mx = fmaxf(mx, v[i]);
        }
        float ssum = 0.f;
#pragma unroll
        for (int i = 0; i < Ldim; i++) ssum += expf(v[i] - mx);
        float nxt = mx + logf(ssum) + e;
        if (act && m > 0) score = nxt;
    }
    float tot = act ? score + endv[j] : -1e30f;
    float mx = tot;
#pragma unroll
    for (int o = 16; o; o >>= 1) mx = fmaxf(mx, __shfl_xor_sync(0xffffffffu, mx, o));
    float ex = act ? expf(tot - mx) : 0.f;
#pragma unroll
    for (int o = 16; o; o >>= 1) ex += __shfl_xor_sync(0xffffffffu, ex, o);
    if (j == 0) logZ[b] = mx + logf(ex);
}

// ---------------- Viterbi ----------------
__global__ void viterbi_kernel(const float* __restrict__ feats, const int* __restrict__ amask,
                               const float* __restrict__ start, const float* __restrict__ endv,
                               const float* __restrict__ trans, int* __restrict__ tags) {
    __shared__ unsigned char hist[(Sdim - 1) * Ldim];
    int b = blockIdx.x;
    int j = threadIdx.x;
    bool act = j < Ldim;
    float tr[Ldim];
#pragma unroll
    for (int i = 0; i < Ldim; i++) tr[i] = act ? trans[i * Ldim + j] : 0.f;
    float score = act ? start[j] + feats[(size_t)(b * Sdim) * Ldim + j] : -1e30f;
    for (int t = 1; t < Sdim; t++) {
        float e = act ? feats[(size_t)(b * Sdim + t) * Ldim + j] : 0.f;
        int m = amask[b * Sdim + t];
        float best = -1e30f;
        int barg = 0;
#pragma unroll
        for (int i = 0; i < Ldim; i++) {
            float si = __shfl_sync(0xffffffffu, score, i);
            float v = si + tr[i];
            if (v > best) { best = v; barg = i; }
        }
        if (act) {
            hist[(t - 1) * Ldim + j] = (unsigned char)barg;
            float nxt = best + e;
            if (m > 0) score = nxt;
        }
    }
    __syncwarp();
    float tot = act ? score + endv[j] : -1e30f;
    float bb = tot;
    int bj = act ? j : 0;
#pragma unroll
    for (int o = 16; o; o >>= 1) {
        float ov = __shfl_down_sync(0xffffffffu, bb, o);
        int oj = __shfl_down_sync(0xffffffffu, bj, o);
        if (ov > bb) { bb = ov; bj = oj; }
    }
    if (j == 0) {
        int tag = bj;
        tags[b * Sdim + Sdim - 1] = tag;
        for (int t = Sdim - 2; t >= 0; t--) {
            tag = hist[t * Ldim + tag];
            tags[b * Sdim + t] = tag;
        }
    }
}

// ---------------- finalize ----------------
__global__ void finalize_kernel(const float* __restrict__ logZ, const float* __restrict__ num,
                                const int* __restrict__ tags, float* __restrict__ out,
                                int out_size) {
    int i = blockIdx.x * blockDim.x + threadIdx.x;
    if (i >= out_size) return;
    if (i == 0) {
        float s = 0.f;
        for (int b = 0; b < Bdim; b++) s += logZ[b] - num[b];
        out[0] = s * (1.f / Bdim);
    } else if (i - 1 < Bdim * Sdim) {
        out[i] = (float)tags[i - 1];
    } else {
        out[i] = 0.f;
    }
}

// ---------------- host launch ----------------
extern "C" void kernel_launch(void* const* d_in, const int* in_sizes, int n_in,
                              void* d_out, int out_size) {
    const float* word_emb = (const float*)d_in[0];
    const float* pos_emb  = (const float*)d_in[1];
    const float* type_emb = (const float*)d_in[2];
    const float* eln_s    = (const float*)d_in[3];
    const float* eln_b    = (const float*)d_in[4];
    const float* Wq = (const float*)d_in[5];
    const float* bq = (const float*)d_in[6];
    const float* Wk = (const float*)d_in[7];
    const float* bk = (const float*)d_in[8];
    const float* Wv = (const float*)d_in[9];
    const float* bv = (const float*)d_in[10];
    const float* Wo = (const float*)d_in[11];
    const float* bo = (const float*)d_in[12];
    const float* ln1s = (const float*)d_in[13];
    const float* ln1b = (const float*)d_in[14];
    const float* W1 = (const float*)d_in[15];
    const float* b1 = (const float*)d_in[16];
    const float* W2 = (const float*)d_in[17];
    const float* b2 = (const float*)d_in[18];
    const float* ln2s = (const float*)d_in[19];
    const float* ln2b = (const float*)d_in[20];
    const float* clfW = (const float*)d_in[21];
    const float* clfb = (const float*)d_in[22];
    const float* crf_start = (const float*)d_in[23];
    const float* crf_end   = (const float*)d_in[24];
    const float* crf_trans = (const float*)d_in[25];
    const int* input_ids   = (const int*)d_in[26];
    const int* token_type  = (const int*)d_in[27];
    const int* attn_mask   = (const int*)d_in[28];
    const int* labels      = (const int*)d_in[29];

    float *h, *q, *k, *v, *t, *feats, *logZ, *num;
    int* tags;
    __nv_bfloat16 *hext, *ctxext, *ffext;
    unsigned int *Wqp, *Wkp, *Wvp, *Wop, *W1p, *W2p;
    cudaGetSymbolAddress((void**)&h, g_h);
    cudaGetSymbolAddress((void**)&q, g_q);
    cudaGetSymbolAddress((void**)&k, g_k);
    cudaGetSymbolAddress((void**)&v, g_v);
    cudaGetSymbolAddress((void**)&t, g_t);
    cudaGetSymbolAddress((void**)&feats, g_feats);
    cudaGetSymbolAddress((void**)&logZ, g_logZ);
    cudaGetSymbolAddress((void**)&num, g_num);
    cudaGetSymbolAddress((void**)&tags, g_tags);
    cudaGetSymbolAddress((void**)&hext, g_hext);
    cudaGetSymbolAddress((void**)&ctxext, g_ctxext);
    cudaGetSymbolAddress((void**)&ffext, g_ffext);
    cudaGetSymbolAddress((void**)&Wqp, g_Wqp);
    cudaGetSymbolAddress((void**)&Wkp, g_Wkp);
    cudaGetSymbolAddress((void**)&Wvp, g_Wvp);
    cudaGetSymbolAddress((void**)&Wop, g_Wop);
    cudaGetSymbolAddress((void**)&W1p, g_W1p);
    cudaGetSymbolAddress((void**)&W2p, g_W2p);

    const int attn_smem = (64 * 512 + 64 * 64 + 64 * 64) * 4;
    cudaFuncSetAttribute(attn_kernel, cudaFuncAttributeMaxDynamicSharedMemorySize, attn_smem);
    cudaFuncSetAttribute(gemm_k1, cudaFuncAttributeMaxDynamicSharedMemorySize, GEMM_SMEM);
    cudaFuncSetAttribute(gemm_k3, cudaFuncAttributeMaxDynamicSharedMemorySize, GEMM_SMEM);

    // weight conversion (every launch; deterministic)
    convB_kernel<<<2048, 256>>>(Wq, Wqp, Hdim, Hdim, NLnum);
    convB_kernel<<<2048, 256>>>(Wk, Wkp, Hdim, Hdim, NLnum);
    convB_kernel<<<2048, 256>>>(Wv, Wvp, Hdim, Hdim, NLnum);
    convB_kernel<<<2048, 256>>>(Wo, Wop, Hdim, Hdim, NLnum);
    convB_kernel<<<4096, 256>>>(W1, W1p, Hdim, FFdim, NLnum);
    convB_kernel<<<4096, 256>>>(W2, W2p, FFdim, Hdim, NLnum);

    embed_ln_kernel<<<Mtot, 256>>>(word_emb, pos_emb, type_emb, eln_s, eln_b,
                                   input_ids, token_type, h, hext);

    dim3 gQKV(Hdim / BN, Mtot / BM, 3);
    dim3 gProj(Hdim / BN, Mtot / BM);
    dim3 gFF1(FFdim / BN, Mtot / BM);
    dim3 gAttn(Sdim / 64, NHnum, Bdim);
    const size_t woff = (size_t)PKH * Hdim;     // 884736
    const size_t w1off = (size_t)PKH * FFdim;   // 3538944
    const size_t w2off = (size_t)PKF * Hdim;    // 3538944

    for (int l = 0; l < NLnum; l++) {
        gemm_k3<<<gQKV, 256, GEMM_SMEM>>>(hext, Wqp + l * woff, Wkp + l * woff, Wvp + l * woff,
                                          bq + l * Hdim, bk + l * Hdim, bv + l * Hdim,
                                          q, k, v, KE_H);
        attn_kernel<<<gAttn, 256, attn_smem>>>(q, k, v, attn_mask, ctxext);
        gemm_k1<<<gProj, 256, GEMM_SMEM>>>(ctxext, Wop + l * woff, bo + l * Hdim, h, t,
                                           nullptr, Hdim, KE_H, 0, 1, 0);
        ln_kernel<<<Mtot, 256>>>(t, ln1s + l * Hdim, ln1b + l * Hdim, h, hext);
        gemm_k1<<<gFF1, 256, GEMM_SMEM>>>(hext, W1p + l * w1off, b1 + l * FFdim, nullptr,
                                          nullptr, ffext, FFdim, KE_H, 1, 0, 1);
        gemm_k1<<<gProj, 256, GEMM_SMEM>>>(ffext, W2p + l * w2off, b2 + l * Hdim, h, t,
                                           nullptr, Hdim, KE_FF, 0, 1, 0);
        ln_kernel<<<Mtot, 256>>>(t, ln2s + l * Hdim, ln2b + l * Hdim, h, hext);
    }

    clf_kernel<<<Mtot, 256>>>(h, clfW, clfb, feats);
    crf_num_kernel<<<Bdim, 256>>>(feats, attn_mask, labels, crf_start, crf_end, crf_trans, num);
    crf_fwd_kernel<<<1, 256>>>(feats, attn_mask, crf_start, crf_end, crf_trans, logZ);
    viterbi_kernel<<<Bdim, 32>>>(feats, attn_mask, crf_start, crf_end, crf_trans, tags);

    int nfin = (out_size + 255) / 256;
    if (nfin < 1) nfin = 1;
    finalize_kernel<<<nfin, 256>>>(logZ, num, tags, (float*)d_out, out_size);
}

// round 6
// speedup vs baseline: 1.5455x; 1.0101x over previous
#include <cuda_runtime.h>
#include <cuda_bf16.h>
#include <math.h>

#define Mtot  4096
#define Hdim  768
#define FFdim 3072
#define NHnum 12
#define DHdim 64
#define Sdim  512
#define Bdim  8
#define Ldim  9
#define NLnum 12

#define KE_H  (3 * Hdim)    // 2304
#define KE_FF (3 * FFdim)   // 9216

// ---------------- scratch (static device allocations) ----------------
__device__ float g_h[Mtot * Hdim];
__device__ float g_q[Mtot * Hdim];
__device__ float g_k[Mtot * Hdim];
__device__ float g_v[Mtot * Hdim];
__device__ float g_t[Mtot * Hdim];
__device__ float g_feats[Mtot * Ldim];
__device__ float g_logZ[Bdim];
__device__ float g_num[Bdim];
__device__ int   g_tags[Bdim * Sdim];

// split-bf16 ext activations (A operands): [M][3K], slots per k: ah, al, ah
__device__ __align__(256) __nv_bfloat16 g_hext[Mtot * KE_H];
__device__ __align__(256) __nv_bfloat16 g_ctxext[Mtot * KE_H];
__device__ __align__(256) __nv_bfloat16 g_ffext[(size_t)Mtot * KE_FF];

// packed split-bf16 weights (B operands): [3K/2][N] u32, pair=(ext row 2i, 2i+1)
// slots per k: bh, bh, bl
#define PKH (3 * Hdim / 2)    // 1152
#define PKF (3 * FFdim / 2)   // 4608
__device__ __align__(256) unsigned int g_Wqp[NLnum * PKH * Hdim];
__device__ __align__(256) unsigned int g_Wkp[NLnum * PKH * Hdim];
__device__ __align__(256) unsigned int g_Wvp[NLnum * PKH * Hdim];
__device__ __align__(256) unsigned int g_Wop[NLnum * PKH * Hdim];
__device__ __align__(256) unsigned int g_W1p[(size_t)NLnum * PKH * FFdim];
__device__ __align__(256) unsigned int g_W2p[(size_t)NLnum * PKF * Hdim];

// ---------------- helpers ----------------
__device__ __forceinline__ float blk_sum256(float v, float* red) {
    int lane = threadIdx.x & 31, w = threadIdx.x >> 5;
#pragma unroll
    for (int o = 16; o; o >>= 1) v += __shfl_xor_sync(0xffffffffu, v, o);
    __syncthreads();
    if (lane == 0) red[w] = v;
    __syncthreads();
    float s = 0.f;
#pragma unroll
    for (int i = 0; i < 8; i++) s += red[i];
    return s;
}

__device__ __forceinline__ void split2(float x, __nv_bfloat16& hi, __nv_bfloat16& lo) {
    hi = __float2bfloat16(x);
    lo = __float2bfloat16(x - __bfloat162float(hi));
}

__device__ __forceinline__ void write_ext3(__nv_bfloat16* p, float x) {
    __nv_bfloat16 h, l;
    split2(x, h, l);
    p[0] = h; p[1] = l; p[2] = h;   // A-ext slots: ah, al, ah
}

// fast exp on the FMA pipe (no MUFU): deg-7 Taylor of 2^f, rel err ~1.3e-6
__device__ __forceinline__ float fexp(float x) {
    float t = x * 1.4426950408889634f;
    t = fmaxf(t, -126.0f);
    float fl = floorf(t);
    float f = t - fl;
    float p = 1.525273e-5f;
    p = fmaf(p, f, 1.5403530e-4f);
    p = fmaf(p, f, 1.3333558e-3f);
    p = fmaf(p, f, 9.6181291e-3f);
    p = fmaf(p, f, 5.5504109e-2f);
    p = fmaf(p, f, 2.4022651e-1f);
    p = fmaf(p, f, 6.9314718e-1f);
    p = fmaf(p, f, 1.0f);
    return p * __int_as_float(((int)fl + 127) << 23);
}

// ---------------- weight conversion: fp32 [L][K][N] -> packed [L][3K/2][N] u32 ---
__global__ void convB_kernel(const float* __restrict__ W, unsigned int* __restrict__ out,
                             int K, int N, int L) {
    size_t PK = (size_t)3 * K / 2;
    size_t total = (size_t)L * PK * N;
    for (size_t idx = (size_t)blockIdx.x * blockDim.x + threadIdx.x; idx < total;
         idx += (size_t)gridDim.x * blockDim.x) {
        int n = (int)(idx % N);
        size_t rest = idx / N;
        int i = (int)(rest % PK);
        int l = (int)(rest / PK);
        int s0 = 2 * i, s1 = 2 * i + 1;
        int k0 = s0 / 3, r0 = s0 % 3;
        int k1 = s1 / 3, r1 = s1 % 3;
        float w0 = W[((size_t)l * K + k0) * N + n];
        float w1 = W[((size_t)l * K + k1) * N + n];
        __nv_bfloat16 h0, l0, h1, l1;
        split2(w0, h0, l0);
        split2(w1, h1, l1);
        __nv_bfloat16 v0 = (r0 == 2) ? l0 : h0;   // B-ext slots: bh, bh, bl
        __nv_bfloat16 v1 = (r1 == 2) ? l1 : h1;
        __nv_bfloat162 pr(v0, v1);
        out[idx] = *reinterpret_cast<unsigned int*>(&pr);
    }
}

// ---------------- embedding + LayerNorm ----------------
__global__ void embed_ln_kernel(const float* __restrict__ we, const float* __restrict__ pe,
                                const float* __restrict__ te, const float* __restrict__ gs,
                                const float* __restrict__ gb, const int* __restrict__ ids,
                                const int* __restrict__ tts, float* __restrict__ out,
                                __nv_bfloat16* __restrict__ ext) {
    __shared__ float red[8];
    int m = blockIdx.x;
    int s = m & (Sdim - 1);
    int id = ids[m], tt = tts[m];
    float vals[3];
    float lsum = 0.f;
#pragma unroll
    for (int u = 0; u < 3; u++) {
        int j = threadIdx.x + u * 256;
        float v = we[(size_t)id * Hdim + j] + pe[(size_t)s * Hdim + j] + te[(size_t)tt * Hdim + j];
        vals[u] = v;
        lsum += v;
    }
    float mean = blk_sum256(lsum, red) * (1.f / Hdim);
    float lsq = 0.f;
#pragma unroll
    for (int u = 0; u < 3; u++) { float d = vals[u] - mean; lsq += d * d; }
    float var = blk_sum256(lsq, red) * (1.f / Hdim);
    float inv = rsqrtf(var + 1e-12f);
#pragma unroll
    for (int u = 0; u < 3; u++) {
        int j = threadIdx.x + u * 256;
        float y = (vals[u] - mean) * inv * gs[j] + gb[j];
        out[(size_t)m * Hdim + j] = y;
        write_ext3(ext + (size_t)m * KE_H + 3 * j, y);
    }
}

// ---------------- LayerNorm ----------------
__global__ void ln_kernel(const float* __restrict__ x, const float* __restrict__ gs,
                          const float* __restrict__ gb, float* __restrict__ y,
                          __nv_bfloat16* __restrict__ ext) {
    __shared__ float red[8];
    int m = blockIdx.x;
    const float* xr = x + (size_t)m * Hdim;
    float vals[3];
    float lsum = 0.f;
#pragma unroll
    for (int u = 0; u < 3; u++) {
        vals[u] = xr[threadIdx.x + u * 256];
        lsum += vals[u];
    }
    float mean = blk_sum256(lsum, red) * (1.f / Hdim);
    float lsq = 0.f;
#pragma unroll
    for (int u = 0; u < 3; u++) { float d = vals[u] - mean; lsq += d * d; }
    float var = blk_sum256(lsq, red) * (1.f / Hdim);
    float inv = rsqrtf(var + 1e-12f);
#pragma unroll
    for (int u = 0; u < 3; u++) {
        int j = threadIdx.x + u * 256;
        float yy = (vals[u] - mean) * inv * gs[j] + gb[j];
        y[(size_t)m * Hdim + j] = yy;
        write_ext3(ext + (size_t)m * KE_H + 3 * j, yy);
    }
}

// ================= tensor-core GEMM (split-bf16, K extended 3x) =================
// 2 CTAs/SM: BKE=48, 4 stages, 107KB smem/CTA
#define BM 128
#define BN 128
#define BKE 48                 // ext bf16 k per tile
#define BKP 24                 // packed pair-rows per tile
#define AS_STRIDE 28           // u32 words per A smem row (24 data + 4 pad)
#define BS_STRIDE 136          // u32 words per B smem row (128 data + 8 pad)
#define STAGE_WORDS (128 * AS_STRIDE + BKP * BS_STRIDE)  // 6848
#define NSTAGE 4
#define GEMM_SMEM (NSTAGE * STAGE_WORDS * 4)             // 109568 B

__device__ __forceinline__ void cp16(unsigned int saddr, const void* gptr) {
    asm volatile("cp.async.cg.shared.global [%0], [%1], 16;\n" ::"r"(saddr), "l"(gptr));
}
__device__ __forceinline__ void cp_commit() { asm volatile("cp.async.commit_group;\n"); }
__device__ __forceinline__ void cp_wait2() { asm volatile("cp.async.wait_group 2;\n"); }

#define MMA16816(d, a, b)                                                      \
    asm volatile(                                                              \
        "mma.sync.aligned.m16n8k16.row.col.f32.bf16.bf16.f32 "                 \
        "{%0,%1,%2,%3}, {%4,%5,%6,%7}, {%8,%9}, {%0,%1,%2,%3};\n"              \
        : "+f"(d[0]), "+f"(d[1]), "+f"(d[2]), "+f"(d[3])                       \
        : "r"(a[0]), "r"(a[1]), "r"(a[2]), "r"(a[3]), "r"(b[0]), "r"(b[1]))

__device__ __forceinline__ void gemm_core(const __nv_bfloat16* __restrict__ A,
                                          const unsigned int* __restrict__ B,
                                          const float* __restrict__ bias,
                                          const float* __restrict__ res,
                                          float* __restrict__ Cf,
                                          __nv_bfloat16* __restrict__ Ce,
                                          int N, int KE, int act, int addres, int outp,
                                          unsigned int* smem) {
    const int tid = threadIdx.x;
    const int lane = tid & 31;
    const int wid = tid >> 5;
    const int warp_m = wid >> 2;   // 0..1
    const int warp_n = wid & 3;    // 0..3
    const int m0 = blockIdx.y * BM;
    const int n0 = blockIdx.x * BN;
    const int T = KE / BKE;
    const int g = lane >> 2, t4 = lane & 3;

    float acc[4][4][4];
#pragma unroll
    for (int i = 0; i < 4; i++)
#pragma unroll
        for (int j = 0; j < 4; j++)
#pragma unroll
            for (int r = 0; r < 4; r++) acc[i][j][r] = 0.f;

    const unsigned int sbase = (unsigned int)__cvta_generic_to_shared(smem);

    auto load_stage = [&](int tile, int stg) {
        unsigned int abase = sbase + (unsigned int)(stg * STAGE_WORDS) * 4u;
        unsigned int bbase = abase + 128u * AS_STRIDE * 4u;
        const __nv_bfloat16* Ag = A + (size_t)m0 * KE + tile * BKE;
#pragma unroll
        for (int l = 0; l < 3; l++) {
            int i = tid + l * 256;
            int r = i / 6, c = i % 6;                // 128 rows x 6 chunks(16B)
            cp16(abase + (unsigned int)(r * AS_STRIDE + c * 4) * 4u,
                 Ag + (size_t)r * KE + c * 8);
        }
        const unsigned int* Bg = B + (size_t)(tile * BKP) * N + n0;
#pragma unroll
        for (int l = 0; l < 3; l++) {
            int i = tid + l * 256;
            int r = i / 32, c = i % 32;              // 24 rows x 32 chunks(16B)
            cp16(bbase + (unsigned int)(r * BS_STRIDE + c * 4) * 4u,
                 Bg + (size_t)r * N + c * 4);
        }
    };

    load_stage(0, 0); cp_commit();
    load_stage(1, 1); cp_commit();
    load_stage(2, 2); cp_commit();

    for (int t = 0; t < T; t++) {
        cp_wait2();
        __syncthreads();
        if (t + 3 < T) load_stage(t + 3, (t + 3) & 3);
        cp_commit();   // ALWAYS commit (empty group at tail) so wait_group N maps to tile t

        const unsigned int* As = smem + (size_t)(t & 3) * STAGE_WORDS;
        const unsigned int* Bs = As + 128 * AS_STRIDE;
#pragma unroll
        for (int s = 0; s < 3; s++) {
            unsigned int a[4][4], b[4][2];
#pragma unroll
            for (int mi = 0; mi < 4; mi++) {
                int r = warp_m * 64 + mi * 16 + g;
                int cp = s * 8 + t4;
                a[mi][0] = As[r * AS_STRIDE + cp];
                a[mi][1] = As[(r + 8) * AS_STRIDE + cp];
                a[mi][2] = As[r * AS_STRIDE + cp + 4];
                a[mi][3] = As[(r + 8) * AS_STRIDE + cp + 4];
            }
#pragma unroll
            for (int nj = 0; nj < 4; nj++) {
                int n = warp_n * 32 + nj * 8 + g;
                b[nj][0] = Bs[(s * 8 + t4) * BS_STRIDE + n];
                b[nj][1] = Bs[(s * 8 + t4 + 4) * BS_STRIDE + n];
            }
#pragma unroll
            for (int mi = 0; mi < 4; mi++)
#pragma unroll
                for (int nj = 0; nj < 4; nj++) MMA16816(acc[mi][nj], a[mi], b[nj]);
        }
        __syncthreads();
    }

    // ---- epilogue ----
#pragma unroll
    for (int mi = 0; mi < 4; mi++) {
        int row0 = m0 + warp_m * 64 + mi * 16 + g;
#pragma unroll
        for (int nj = 0; nj < 4; nj++) {
            int col = n0 + warp_n * 32 + nj * 8 + t4 * 2;
            float b0 = bias[col], b1 = bias[col + 1];
#pragma unroll
            for (int half = 0; half < 2; half++) {
                int row = row0 + half * 8;
                float v0 = acc[mi][nj][half * 2 + 0] + b0;
                float v1 = acc[mi][nj][half * 2 + 1] + b1;
                if (addres) {
                    float2 rr = *(const float2*)(res + (size_t)row * N + col);
                    v0 += rr.x;
                    v1 += rr.y;
                }
                if (act) {
                    v0 = 0.5f * v0 * (1.f + erff(v0 * 0.70710678118654752440f));
                    v1 = 0.5f * v1 * (1.f + erff(v1 * 0.70710678118654752440f));
                }
                if (outp == 0) {
                    *(float2*)(Cf + (size_t)row * N + col) = make_float2(v0, v1);
                } else {
                    __nv_bfloat16* p = Ce + (size_t)row * (3 * N) + 3 * col;
                    write_ext3(p, v0);
                    write_ext3(p + 3, v1);
                }
            }
        }
    }
}

__global__ void __launch_bounds__(256, 2) gemm_k1(const __nv_bfloat16* __restrict__ A,
                                                  const unsigned int* __restrict__ B,
                                                  const float* __restrict__ bias,
                                                  const float* __restrict__ res,
                                                  float* __restrict__ Cf,
                                                  __nv_bfloat16* __restrict__ Ce,
                                                  int N, int KE, int act, int addres, int outp) {
    extern __shared__ unsigned int smem[];
    gemm_core(A, B, bias, res, Cf, Ce, N, KE, act, addres, outp, smem);
}

__global__ void __launch_bounds__(256, 2) gemm_k3(const __nv_bfloat16* __restrict__ A,
                                                  const unsigned int* __restrict__ B0,
                                                  const unsigned int* __restrict__ B1,
                                                  const unsigned int* __restrict__ B2,
                                                  const float* __restrict__ bias0,
                                                  const float* __restrict__ bias1,
                                                  const float* __restrict__ bias2,
                                                  float* __restrict__ C0, float* __restrict__ C1,
                                                  float* __restrict__ C2, int KE) {
    extern __shared__ unsigned int smem[];
    int z = blockIdx.z;
    const unsigned int* B = (z == 0) ? B0 : (z == 1) ? B1 : B2;
    const float* bias = (z == 0) ? bias0 : (z == 1) ? bias1 : bias2;
    float* Cf = (z == 0) ? C0 : (z == 1) ? C1 : C2;
    gemm_core(A, B, bias, nullptr, Cf, nullptr, Hdim, KE, 0, 0, 0, smem);
}

// ---------------- attention (fp32 SIMT; fast exp; epilogue emits split-bf16 ext) --------
__global__ void __launch_bounds__(256) attn_kernel(const float* __restrict__ Q,
                                                   const float* __restrict__ Kp,
                                                   const float* __restrict__ Vp,
                                                   const int* __restrict__ amask,
                                                   __nv_bfloat16* __restrict__ Oext) {
    extern __shared__ float sm[];
    float* sc = sm;
    float* qT = sm + 64 * 512;
    float* kT = qT + 64 * 64;
    const int tid = threadIdx.x;
    const int q0 = blockIdx.x * 64;
    const int h = blockIdx.y;
    const int b = blockIdx.z;
    const size_t base = (size_t)b * Sdim * Hdim + h * 64;
    const int ty = tid >> 4, tx = tid & 15;

    for (int i = tid; i < 1024; i += 256) {
        int r = i >> 4, c4 = i & 15;
        float4 v = *(const float4*)(Q + base + (size_t)(q0 + r) * Hdim + c4 * 4);
        qT[(c4 * 4 + 0) * 64 + r] = v.x;
        qT[(c4 * 4 + 1) * 64 + r] = v.y;
        qT[(c4 * 4 + 2) * 64 + r] = v.z;
        qT[(c4 * 4 + 3) * 64 + r] = v.w;
    }

    for (int kt = 0; kt < 8; kt++) {
        int k0 = kt * 64;
        __syncthreads();
        for (int i = tid; i < 1024; i += 256) {
            int r = i >> 4, c4 = i & 15;
            float4 v = *(const float4*)(Kp + base + (size_t)(k0 + r) * Hdim + c4 * 4);
            kT[(c4 * 4 + 0) * 64 + r] = v.x;
            kT[(c4 * 4 + 1) * 64 + r] = v.y;
            kT[(c4 * 4 + 2) * 64 + r] = v.z;
            kT[(c4 * 4 + 3) * 64 + r] = v.w;
        }
        __syncthreads();
        float acc[4][4];
#pragma unroll
        for (int i = 0; i < 4; i++)
#pragma unroll
            for (int j = 0; j < 4; j++) acc[i][j] = 0.f;
        for (int d = 0; d < 64; d++) {
            float a[4], bb[4];
            *(float4*)a = *(const float4*)(&qT[d * 64 + ty * 4]);
            *(float4*)bb = *(const float4*)(&kT[d * 64 + tx * 4]);
#pragma unroll
            for (int i = 0; i < 4; i++)
#pragma unroll
                for (int j = 0; j < 4; j++) acc[i][j] += a[i] * bb[j];
        }
#pragma unroll
        for (int i = 0; i < 4; i++) {
            float4 v = make_float4(acc[i][0], acc[i][1], acc[i][2], acc[i][3]);
            *(float4*)(&sc[(ty * 4 + i) * 512 + k0 + tx * 4]) = v;
        }
    }
    __syncthreads();

    {
        int row = tid >> 2, lane = tid & 3;
        float mx = -1e30f;
        for (int k = lane; k < 512; k += 4) {
            float mb = (1.f - (float)amask[b * Sdim + k]) * -10000.f;
            float v = sc[row * 512 + k] * 0.125f + mb;
            sc[row * 512 + k] = v;
            mx = fmaxf(mx, v);
        }
        mx = fmaxf(mx, __shfl_xor_sync(0xffffffffu, mx, 1, 4));
        mx = fmaxf(mx, __shfl_xor_sync(0xffffffffu, mx, 2, 4));
        float sum = 0.f;
        for (int k = lane; k < 512; k += 4) {
            float e = fexp(sc[row * 512 + k] - mx);
            sc[row * 512 + k] = e;
            sum += e;
        }
        sum += __shfl_xor_sync(0xffffffffu, sum, 1, 4);
        sum += __shfl_xor_sync(0xffffffffu, sum, 2, 4);
        float inv = 1.f / sum;
        for (int k = lane; k < 512; k += 4) sc[row * 512 + k] *= inv;
    }

    float acc[4][4];
#pragma unroll
    for (int i = 0; i < 4; i++)
#pragma unroll
        for (int j = 0; j < 4; j++) acc[i][j] = 0.f;
    for (int kt = 0; kt < 8; kt++) {
        int k0 = kt * 64;
        __syncthreads();
        for (int i = tid; i < 1024; i += 256) {
            int r = i >> 4, c4 = i & 15;
            float4 v = *(const float4*)(Vp + base + (size_t)(k0 + r) * Hdim + c4 * 4);
            *(float4*)(&kT[r * 64 + c4 * 4]) = v;
        }
        __syncthreads();
        for (int kk = 0; kk < 64; kk++) {
            float bb[4];
            *(float4*)bb = *(const float4*)(&kT[kk * 64 + tx * 4]);
            float p0 = sc[(ty * 4 + 0) * 512 + k0 + kk];
            float p1 = sc[(ty * 4 + 1) * 512 + k0 + kk];
            float p2 = sc[(ty * 4 + 2) * 512 + k0 + kk];
            float p3 = sc[(ty * 4 + 3) * 512 + k0 + kk];
#pragma unroll
            for (int j = 0; j < 4; j++) {
                acc[0][j] += p0 * bb[j];
                acc[1][j] += p1 * bb[j];
                acc[2][j] += p2 * bb[j];
                acc[3][j] += p3 * bb[j];
            }
        }
    }
#pragma unroll
    for (int i = 0; i < 4; i++) {
        int m = b * Sdim + q0 + ty * 4 + i;
        int colbase = h * 64 + tx * 4;
        __nv_bfloat16* p = Oext + (size_t)m * KE_H + 3 * colbase;
#pragma unroll
        for (int j = 0; j < 4; j++) write_ext3(p + 3 * j, acc[i][j]);
    }
}

// ---------------- classifier ----------------
__global__ void clf_kernel(const float* __restrict__ X, const float* __restrict__ W,
                           const float* __restrict__ bias, float* __restrict__ F) {
    __shared__ float red[8][Ldim];
    int m = blockIdx.x;
    int tid = threadIdx.x;
    float acc[Ldim];
#pragma unroll
    for (int j = 0; j < Ldim; j++) acc[j] = 0.f;
    for (int k = tid; k < Hdim; k += 256) {
        float x = X[(size_t)m * Hdim + k];
#pragma unroll
        for (int j = 0; j < Ldim; j++) acc[j] += x * W[k * Ldim + j];
    }
    int lane = tid & 31, w = tid >> 5;
#pragma unroll
    for (int j = 0; j < Ldim; j++)
#pragma unroll
        for (int o = 16; o; o >>= 1) acc[j] += __shfl_down_sync(0xffffffffu, acc[j], o);
    if (lane == 0)
#pragma unroll
        for (int j = 0; j < Ldim; j++) red[w][j] = acc[j];
    __syncthreads();
    if (tid < Ldim) {
        float s = bias[tid];
#pragma unroll
        for (int ww = 0; ww < 8; ww++) s += red[ww][tid];
        F[(size_t)m * Ldim + tid] = s;
    }
}

// ---------------- CRF numerator ----------------
__global__ void crf_num_kernel(const float* __restrict__ feats, const int* __restrict__ amask,
                               const int* __restrict__ labels, const float* __restrict__ start,
                               const float* __restrict__ endv, const float* __restrict__ trans,
                               float* __restrict__ num) {
    __shared__ float red[8];
    int b = blockIdx.x;
    int tid = threadIdx.x;
    float s = 0.f, msum = 0.f;
    for (int t = tid; t < Sdim; t += 256) {
        int tag = labels[b * Sdim + t];
        float em = feats[(size_t)(b * Sdim + t) * Ldim + tag];
        float m = (float)amask[b * Sdim + t];
        msum += m;
        if (t == 0) {
            s += start[tag] + em;
        } else {
            int pt = labels[b * Sdim + t - 1];
            s += (em + trans[pt * Ldim + tag]) * m;
        }
    }
    float stotal = blk_sum256(s, red);
    float mtotal = blk_sum256(msum, red);
    if (tid == 0) {
        int last = (int)(mtotal + 0.5f) - 1;
        num[b] = stotal + endv[labels[b * Sdim + last]];
    }
}

// ---------------- CRF forward ----------------
__global__ void crf_fwd_kernel(const float* __restrict__ feats, const int* __restrict__ amask,
                               const float* __restrict__ start, const float* __restrict__ endv,
                               const float* __restrict__ trans, float* __restrict__ logZ) {
    int b = threadIdx.x >> 5;
    int j = threadIdx.x & 31;
    bool act = j < Ldim;
    float tr[Ldim];
#pragma unroll
    for (int i = 0; i < Ldim; i++) tr[i] = act ? trans[i * Ldim + j] : 0.f;
    float score = act ? start[j] + feats[(size_t)(b * Sdim) * Ldim + j] : -1e30f;
    for (int t = 1; t < Sdim; t++) {
        float e = act ? feats[(size_t)(b * Sdim + t) * Ldim + j] : 0.f;
        int m = amask[b * Sdim + t];
        float v[Ldim];
        float mx = -1e30f;
#pragma unroll
        for (int i = 0; i < Ldim; i++) {
            float si = __shfl_sync(0xffffffffu, score, i);
            v[i] = si + tr[i];
            mx = fmaxf(mx, v[i]);
        }
        float ssum = 0.f;
#pragma unroll
        for (int i = 0; i < Ldim; i++) ssum += expf(v[i] - mx);
        float nxt = mx + logf(ssum) + e;
        if (act && m > 0) score = nxt;
    }
    float tot = act ? score + endv[j] : -1e30f;
    float mx = tot;
#pragma unroll
    for (int o = 16; o; o >>= 1) mx = fmaxf(mx, __shfl_xor_sync(0xffffffffu, mx, o));
    float ex = act ? expf(tot - mx) : 0.f;
#pragma unroll
    for (int o = 16; o; o >>= 1) ex += __shfl_xor_sync(0xffffffffu, ex, o);
    if (j == 0) logZ[b] = mx + logf(ex);
}

// ---------------- Viterbi ----------------
__global__ void viterbi_kernel(const float* __restrict__ feats, const int* __restrict__ amask,
                               const float* __restrict__ start, const float* __restrict__ endv,
                               const float* __restrict__ trans, int* __restrict__ tags) {
    __shared__ unsigned char hist[(Sdim - 1) * Ldim];
    int b = blockIdx.x;
    int j = threadIdx.x;
    bool act = j < Ldim;
    float tr[Ldim];
#pragma unroll
    for (int i = 0; i < Ldim; i++) tr[i] = act ? trans[i * Ldim + j] : 0.f;
    float score = act ? start[j] + feats[(size_t)(b * Sdim) * Ldim + j] : -1e30f;
    for (int t = 1; t < Sdim; t++) {
        float e = act ? feats[(size_t)(b * Sdim + t) * Ldim + j] : 0.f;
        int m = amask[b * Sdim + t];
        float best = -1e30f;
        int barg = 0;
#pragma unroll
        for (int i = 0; i < Ldim; i++) {
            float si = __shfl_sync(0xffffffffu, score, i);
            float v = si + tr[i];
            if (v > best) { best = v; barg = i; }
        }
        if (act) {
            hist[(t - 1) * Ldim + j] = (unsigned char)barg;
            float nxt = best + e;
            if (m > 0) score = nxt;
        }
    }
    __syncwarp();
    float tot = act ? score + endv[j] : -1e30f;
    float bb = tot;
    int bj = act ? j : 0;
#pragma unroll
    for (int o = 16; o; o >>= 1) {
        float ov = __shfl_down_sync(0xffffffffu, bb, o);
        int oj = __shfl_down_sync(0xffffffffu, bj, o);
        if (ov > bb) { bb = ov; bj = oj; }
    }
    if (j == 0) {
        int tag = bj;
        tags[b * Sdim + Sdim - 1] = tag;
        for (int t = Sdim - 2; t >= 0; t--) {
            tag = hist[t * Ldim + tag];
            tags[b * Sdim + t] = tag;
        }
    }
}

// ---------------- finalize ----------------
__global__ void finalize_kernel(const float* __restrict__ logZ, const float* __restrict__ num,
                                const int* __restrict__ tags, float* __restrict__ out,
                                int out_size) {
    int i = blockIdx.x * blockDim.x + threadIdx.x;
    if (i >= out_size) return;
    if (i == 0) {
        float s = 0.f;
        for (int b = 0; b < Bdim; b++) s += logZ[b] - num[b];
        out[0] = s * (1.f / Bdim);
    } else if (i - 1 < Bdim * Sdim) {
        out[i] = (float)tags[i - 1];
    } else {
        out[i] = 0.f;
    }
}

// ---------------- host launch ----------------
extern "C" void kernel_launch(void* const* d_in, const int* in_sizes, int n_in,
                              void* d_out, int out_size) {
    const float* word_emb = (const float*)d_in[0];
    const float* pos_emb  = (const float*)d_in[1];
    const float* type_emb = (const float*)d_in[2];
    const float* eln_s    = (const float*)d_in[3];
    const float* eln_b    = (const float*)d_in[4];
    const float* Wq = (const float*)d_in[5];
    const float* bq = (const float*)d_in[6];
    const float* Wk = (const float*)d_in[7];
    const float* bk = (const float*)d_in[8];
    const float* Wv = (const float*)d_in[9];
    const float* bv = (const float*)d_in[10];
    const float* Wo = (const float*)d_in[11];
    const float* bo = (const float*)d_in[12];
    const float* ln1s = (const float*)d_in[13];
    const float* ln1b = (const float*)d_in[14];
    const float* W1 = (const float*)d_in[15];
    const float* b1 = (const float*)d_in[16];
    const float* W2 = (const float*)d_in[17];
    const float* b2 = (const float*)d_in[18];
    const float* ln2s = (const float*)d_in[19];
    const float* ln2b = (const float*)d_in[20];
    const float* clfW = (const float*)d_in[21];
    const float* clfb = (const float*)d_in[22];
    const float* crf_start = (const float*)d_in[23];
    const float* crf_end   = (const float*)d_in[24];
    const float* crf_trans = (const float*)d_in[25];
    const int* input_ids   = (const int*)d_in[26];
    const int* token_type  = (const int*)d_in[27];
    const int* attn_mask   = (const int*)d_in[28];
    const int* labels      = (const int*)d_in[29];

    float *h, *q, *k, *v, *t, *feats, *logZ, *num;
    int* tags;
    __nv_bfloat16 *hext, *ctxext, *ffext;
    unsigned int *Wqp, *Wkp, *Wvp, *Wop, *W1p, *W2p;
    cudaGetSymbolAddress((void**)&h, g_h);
    cudaGetSymbolAddress((void**)&q, g_q);
    cudaGetSymbolAddress((void**)&k, g_k);
    cudaGetSymbolAddress((void**)&v, g_v);
    cudaGetSymbolAddress((void**)&t, g_t);
    cudaGetSymbolAddress((void**)&feats, g_feats);
    cudaGetSymbolAddress((void**)&logZ, g_logZ);
    cudaGetSymbolAddress((void**)&num, g_num);
    cudaGetSymbolAddress((void**)&tags, g_tags);
    cudaGetSymbolAddress((void**)&hext, g_hext);
    cudaGetSymbolAddress((void**)&ctxext, g_ctxext);
    cudaGetSymbolAddress((void**)&ffext, g_ffext);
    cudaGetSymbolAddress((void**)&Wqp, g_Wqp);
    cudaGetSymbolAddress((void**)&Wkp, g_Wkp);
    cudaGetSymbolAddress((void**)&Wvp, g_Wvp);
    cudaGetSymbolAddress((void**)&Wop, g_Wop);
    cudaGetSymbolAddress((void**)&W1p, g_W1p);
    cudaGetSymbolAddress((void**)&W2p, g_W2p);

    const int attn_smem = (64 * 512 + 64 * 64 + 64 * 64) * 4;
    cudaFuncSetAttribute(attn_kernel, cudaFuncAttributeMaxDynamicSharedMemorySize, attn_smem);
    cudaFuncSetAttribute(gemm_k1, cudaFuncAttributeMaxDynamicSharedMemorySize, GEMM_SMEM);
    cudaFuncSetAttribute(gemm_k3, cudaFuncAttributeMaxDynamicSharedMemorySize, GEMM_SMEM);

    convB_kernel<<<2048, 256>>>(Wq, Wqp, Hdim, Hdim, NLnum);
    convB_kernel<<<2048, 256>>>(Wk, Wkp, Hdim, Hdim, NLnum);
    convB_kernel<<<2048, 256>>>(Wv, Wvp, Hdim, Hdim, NLnum);
    convB_kernel<<<2048, 256>>>(Wo, Wop, Hdim, Hdim, NLnum);
    convB_kernel<<<4096, 256>>>(W1, W1p, Hdim, FFdim, NLnum);
    convB_kernel<<<4096, 256>>>(W2, W2p, FFdim, Hdim, NLnum);

    embed_ln_kernel<<<Mtot, 256>>>(word_emb, pos_emb, type_emb, eln_s, eln_b,
                                   input_ids, token_type, h, hext);

    dim3 gQKV(Hdim / BN, Mtot / BM, 3);
    dim3 gProj(Hdim / BN, Mtot / BM);
    dim3 gFF1(FFdim / BN, Mtot / BM);
    dim3 gAttn(Sdim / 64, NHnum, Bdim);
    const size_t woff = (size_t)PKH * Hdim;
    const size_t w1off = (size_t)PKH * FFdim;
    const size_t w2off = (size_t)PKF * Hdim;

    for (int l = 0; l < NLnum; l++) {
        gemm_k3<<<gQKV, 256, GEMM_SMEM>>>(hext, Wqp + l * woff, Wkp + l * woff, Wvp + l * woff,
                                          bq + l * Hdim, bk + l * Hdim, bv + l * Hdim,
                                          q, k, v, KE_H);
        attn_kernel<<<gAttn, 256, attn_smem>>>(q, k, v, attn_mask, ctxext);
        gemm_k1<<<gProj, 256, GEMM_SMEM>>>(ctxext, Wop + l * woff, bo + l * Hdim, h, t,
                                           nullptr, Hdim, KE_H, 0, 1, 0);
        ln_kernel<<<Mtot, 256>>>(t, ln1s + l * Hdim, ln1b + l * Hdim, h, hext);
        gemm_k1<<<gFF1, 256, GEMM_SMEM>>>(hext, W1p + l * w1off, b1 + l * FFdim, nullptr,
                                          nullptr, ffext, FFdim, KE_H, 1, 0, 1);
        gemm_k1<<<gProj, 256, GEMM_SMEM>>>(ffext, W2p + l * w2off, b2 + l * Hdim, h, t,
                                           nullptr, Hdim, KE_FF, 0, 1, 0);
        ln_kernel<<<Mtot, 256>>>(t, ln2s + l * Hdim, ln2b + l * Hdim, h, hext);
    }

    clf_kernel<<<Mtot, 256>>>(h, clfW, clfb, feats);
    crf_num_kernel<<<Bdim, 256>>>(feats, attn_mask, labels, crf_start, crf_end, crf_trans, num);
    crf_fwd_kernel<<<1, 256>>>(feats, attn_mask, crf_start, crf_end, crf_trans, logZ);
    viterbi_kernel<<<Bdim, 32>>>(feats, attn_mask, crf_start, crf_end, crf_trans, tags);

    int nfin = (out_size + 255) / 256;
    if (nfin < 1) nfin = 1;
    finalize_kernel<<<nfin, 256>>>(logZ, num, tags, (float*)d_out, out_size);
}